// round 6
// baseline (speedup 1.0000x reference)
#include <cuda_runtime.h>

// SimplePhotonicRaytracer — GB300 sm_103a
//
// DESIGN (held since R2; audited every round since, no defects found; still
// awaiting the first successful GB300 hold):
// The optical response depends only on (cell 0..80, digit 0..9) -> 810-entry
// LUT. Kernel 1 (810 threads) computes all transcendentals once. Kernel 2 is
// a grid-stride streaming gather at the DRAM roofline: int4 grid load ->
// shared-LUT lookup -> 7x STG.128 per 4 cells. Fixed small grid (<=1184
// blocks) keeps the per-block LUT broadcast at ~19 MB of L2 traffic.
//
// Output layout: d_out = [ feats (B*81*4 f32) | resp (B*81*3 f32) ]
// (tuple return order of the reference). The split offset is derived from
// out_size (= 7 * ncells) so it is robust to how in_sizes reports counts.
// If the first bench shows structural rel_err, swap the segments first.

#define GCELLS 81
#define NDIG   10
#define NLUT   (GCELLS * NDIG)
#define BLOCK  256
#define GRID   1184   // 148 SMs * 8

__device__ float4 g_lut[NLUT];     // {r0, r1, r2, mean}
__device__ float  g_lutvar[NLUT];  // unbiased var (ddof=1)

__global__ void build_lut_kernel(const float* __restrict__ ri,     // [81]
                                 const float* __restrict__ absorb, // [81*3]
                                 const float* __restrict__ tsp)    // [1]
{
    int e = blockIdx.x * blockDim.x + threadIdx.x;
    if (e >= NLUT) return;
    int c = e / NDIG;     // cell 0..80
    int d = e % NDIG;     // digit 0..9

    float n  = ri[c];
    float ts = *tsp;

    // heights = BASE_HEIGHT + thickness_scale * digit ; path = heights * n
    float height = 1e-4f + ts * (float)d;
    float path   = height * n;

    // Fresnel reflectance at normal incidence: R = ((1-n)/(1+n))^2
    float rr = (1.0f - n) / (1.0f + n);
    float tf = 1.0f - rr * rr;

    const float lam[3] = {6.5e-7f, 5.5e-7f, 4.5e-7f};
    float twopi_path = 6.283185307179586f * path;   // (2*pi*path)/lambda, ref op order

    float r[3];
#pragma unroll
    for (int w = 0; w < 3; ++w) {
        float alpha  = fabsf(absorb[c * 3 + w]);
        float trans  = expf(-alpha * path);                       // Beer's law
        float interf = 0.5f * (1.0f + cosf(twopi_path / lam[w])); // interference
        r[w] = tf * trans * interf;
    }

    float mean = (r[0] + r[1] + r[2]) * (1.0f / 3.0f);
    float d0 = r[0] - mean, d1 = r[1] - mean, d2 = r[2] - mean;
    float var = (d0 * d0 + d1 * d1 + d2 * d2) * 0.5f;   // ddof=1, W=3 -> /2

    g_lut[e]    = make_float4(r[0], r[1], r[2], mean);
    g_lutvar[e] = var;
}

__global__ void __launch_bounds__(BLOCK)
photonic_main_kernel(const int* __restrict__ grid,   // [B*81]
                     float* __restrict__ feats,      // [B*81*4]
                     float* __restrict__ resp,       // [B*81*3]
                     int total)                      // B*81, divisible by 4
{
    __shared__ float4 sLut[NLUT];   // {r0,r1,r2,mean}
    __shared__ float  sVar[NLUT];
    __shared__ float  sMean[NLUT];  // scalar mean for neighbor probes (LDS.32)

    for (int k = threadIdx.x; k < NLUT; k += BLOCK) {
        float4 v = g_lut[k];
        sLut[k]  = v;
        sVar[k]  = g_lutvar[k];
        sMean[k] = v.w;
    }
    __syncthreads();

    const int4* grid4  = reinterpret_cast<const int4*>(grid);
    float4*     feats4 = reinterpret_cast<float4*>(feats);
    float4*     resp4  = reinterpret_cast<float4*>(resp);

    int ngroups = total >> 2;
    int stride  = gridDim.x * blockDim.x;

    for (int v = blockIdx.x * blockDim.x + threadIdx.x; v < ngroups; v += stride) {
        int base = v << 2;

        // cell indices for the 4 elements (c0..c0+3 mod 81)
        int c0 = base % GCELLS;
        int cc[4];
#pragma unroll
        for (int k = 0; k < 4; ++k) {
            int c = c0 + k; if (c >= GCELLS) c -= GCELLS;
            cc[k] = c;
        }

        // ---- front-batch ALL global loads (raise MLP before any LDS) ----
        int4 g4 = grid4[v];
        int dig[4] = {g4.x, g4.y, g4.z, g4.w};

        int ndn[4];   // +9 (row) neighbor digits; guard row<8 keeps loads in-board
#pragma unroll
        for (int k = 0; k < 4; ++k)
            ndn[k] = (cc[k] < 72) ? __ldg(&grid[base + k + 9]) : 0;

        // +1 (col) neighbor for k=3; k<3 neighbors come from registers (dig[k+1])
        int nd3 = (cc[3] % 9 < 8) ? __ldg(&grid[base + 4]) : 0;

        // ---- LUT lookups + feature assembly ----
        float rbuf[12];
        float4 fbuf[4];
#pragma unroll
        for (int k = 0; k < 4; ++k) {
            int c = cc[k];
            int j = c % 9;

            int e = c * NDIG + dig[k];
            float4 rm  = sLut[e];
            float  var = sVar[e];

            // diff with append(last) => 0 at j==8 / row==8
            float gx = 0.0f, gy = 0.0f;
            if (j < 8) {
                int dr = (k < 3) ? dig[k + 1] : nd3;
                gx = sMean[(c + 1) * NDIG + dr] - rm.w;
            }
            if (c < 72)   // row < 8
                gy = sMean[(c + 9) * NDIG + ndn[k]] - rm.w;

            rbuf[k * 3 + 0] = rm.x;
            rbuf[k * 3 + 1] = rm.y;
            rbuf[k * 3 + 2] = rm.z;
            fbuf[k] = make_float4(rm.w, var, gx, gy);
        }

        // ---- stores: 4x STG.128 feats + 3x STG.128 resp (all 16B-aligned) ----
#pragma unroll
        for (int k = 0; k < 4; ++k)
            feats4[base + k] = fbuf[k];

        int rb = v * 3;
#pragma unroll
        for (int k = 0; k < 3; ++k)
            resp4[rb + k] = make_float4(rbuf[k * 4 + 0], rbuf[k * 4 + 1],
                                        rbuf[k * 4 + 2], rbuf[k * 4 + 3]);
    }
}

extern "C" void kernel_launch(void* const* d_in, const int* in_sizes, int n_in,
                              void* d_out, int out_size)
{
    const int*   grid = (const int*)d_in[0];     // sudoku_grid  [B,9,9] int32
    const float* ri   = (const float*)d_in[1];   // refractive_indices [9,9]
    const float* ab   = (const float*)d_in[2];   // absorption_coeffs  [9,9,3]
    const float* ts   = (const float*)d_in[3];   // thickness_scale    [1]

    // ncells derived from out_size: out = feats(4/cell) + resp(3/cell) = 7/cell.
    // (Matches in_sizes[0] = B*81; this form is robust either way.)
    int total = out_size / 7;

    float* feats = (float*)d_out;
    float* resp  = (float*)d_out + (size_t)total * 4;

    build_lut_kernel<<<(NLUT + 255) / 256, 256>>>(ri, ab, ts);

    int ngroups = total >> 2;
    int nblocks = (ngroups + BLOCK - 1) / BLOCK;
    if (nblocks > GRID) nblocks = GRID;
    photonic_main_kernel<<<nblocks, BLOCK>>>(grid, feats, resp, total);
}